// round 15
// baseline (speedup 1.0000x reference)
#include <cuda_runtime.h>
#include <cuda_bf16.h>
#include <cstdint>

#define VV 50000
#define VVP 50048            // padded vocab
#define TT 200
#define TTP 208              // padded topic dim (13*16)
#define KEMB 512
#define BB 2048
#define TK 20
#define NSEG 2
#define SEGLEN 25000

// ------------------------- static device scratch -------------------------
// g_wtb holds e = exp(wt) in bf16 (written directly by wt_mma's epilogue; no max shift
// needed since |wt| <= ~0.35). Padding rows/cols stay zero from static init.
__device__ __align__(16) __nv_bfloat16 g_wtb[(size_t)TTP * VVP];
__device__ __align__(16) __nv_bfloat16 g_thb[(size_t)BB * TTP]; // theta' = theta * rowinv[t]
__device__ __align__(16) float g_segsum[TT * NSEG];
__device__ __align__(16) float g_cand_v[TT * NSEG * TK];
__device__ __align__(16) int   g_cand_i[TT * NSEG * TK];
__device__ __align__(16) float g_topv[TT * TK];
__device__ __align__(16) int   g_topi[TT * TK];
__device__ __align__(16) float g_sq[TT];
__device__ __align__(16) float g_rowinv[TT];

// ------------------------- helpers -------------------------
__device__ __forceinline__ uint32_t smem_u32(const void* p) {
    return (uint32_t)__cvta_generic_to_shared(p);
}
__device__ __forceinline__ void ldsm_x4(uint32_t& r0, uint32_t& r1, uint32_t& r2, uint32_t& r3,
                                        uint32_t addr) {
    asm volatile("ldmatrix.sync.aligned.m8n8.x4.shared.b16 {%0,%1,%2,%3}, [%4];\n"
                 : "=r"(r0), "=r"(r1), "=r"(r2), "=r"(r3) : "r"(addr));
}
__device__ __forceinline__ void mma_bf16(float* d, const uint32_t* a, const uint32_t* b) {
    asm volatile(
        "mma.sync.aligned.m16n8k16.row.col.f32.bf16.bf16.f32 "
        "{%0,%1,%2,%3},{%4,%5,%6,%7},{%8,%9},{%0,%1,%2,%3};\n"
        : "+f"(d[0]), "+f"(d[1]), "+f"(d[2]), "+f"(d[3])
        : "r"(a[0]), "r"(a[1]), "r"(a[2]), "r"(a[3]), "r"(b[0]), "r"(b[1]));
}
__device__ __forceinline__ void mma_bf16_k8(float* d, uint32_t a0, uint32_t a1, uint32_t b0) {
    asm volatile(
        "mma.sync.aligned.m16n8k8.row.col.f32.bf16.bf16.f32 "
        "{%0,%1,%2,%3},{%4,%5},{%6},{%0,%1,%2,%3};\n"
        : "+f"(d[0]), "+f"(d[1]), "+f"(d[2]), "+f"(d[3])
        : "r"(a0), "r"(a1), "r"(b0));
}
__device__ __forceinline__ void prefetch_l2(const void* p) {
    asm volatile("prefetch.global.L2 [%0];\n" :: "l"(p));
}
// exp(x) for |x| <= ~0.4: degree-8 Taylor/Horner on the FMA pipe. abs err < 3e-10.
__device__ __forceinline__ float exp_poly(float x) {
    float r = 2.4801587e-5f;
    r = fmaf(r, x, 1.9841270e-4f);
    r = fmaf(r, x, 1.3888889e-3f);
    r = fmaf(r, x, 8.3333333e-3f);
    r = fmaf(r, x, 4.1666667e-2f);
    r = fmaf(r, x, 1.6666667e-1f);
    r = fmaf(r, x, 0.5f);
    r = fmaf(r, x, 1.0f);
    r = fmaf(r, x, 1.0f);
    return r;
}
__device__ __forceinline__ unsigned long long makekey(float v, int i) {
    // valid for v >= 0
    return ((unsigned long long)__float_as_uint(v) << 32) |
           (unsigned long long)(0xFFFFFFFFu - (unsigned)i);
}

// ------------------------- theta = softmax(alpha) -------------------------
__global__ void theta_kernel(const float* __restrict__ alpha, float* __restrict__ theta) {
    int row = blockIdx.x;
    int tid = threadIdx.x;
    __shared__ float red[256];
    float x = (tid < TT) ? alpha[row * TT + tid] : -1e30f;
    red[tid] = x;
    __syncthreads();
    for (int s = 128; s > 0; s >>= 1) {
        if (tid < s) red[tid] = fmaxf(red[tid], red[tid + s]);
        __syncthreads();
    }
    float m = red[0];
    __syncthreads();
    float e = (tid < TT) ? __expf(x - m) : 0.f;
    red[tid] = e;
    __syncthreads();
    for (int s = 128; s > 0; s >>= 1) {
        if (tid < s) red[tid] += red[tid + s];
        __syncthreads();
    }
    float inv = 1.f / red[0];
    if (tid < TT) theta[row * TT + tid] = e * inv;
}

// ------------------------- wt_mma: e = exp(topic_emb @ word_emb), bf16 out ----------------
// grid ((VV+127)/128, 2), x = vocab (fast / streaming), y = bm.
// A staged directly from fp32 temb (inline bf16 conversion); no max subtraction needed.
__global__ __launch_bounds__(256, 2) void wt_mma_kernel(const float* __restrict__ temb,
                                                        const float* __restrict__ wemb) {
    __shared__ __align__(16) __nv_bfloat16 As[2][128 * 24];
    __shared__ __align__(16) __nv_bfloat16 Bs[2][16 * 136];
    const int tid = threadIdx.x, lane = tid & 31, wid = tid >> 5;
    const int warp_m = wid >> 2, warp_n = wid & 3;
    const int bm = blockIdx.y * 128, vb = blockIdx.x * 128;
    const int a_row = tid >> 1, a_half = tid & 1;
    const int b_row = tid >> 4, b_seg = tid & 15;
    const int bcol = vb + b_seg * 8;
    const bool arow_ok = (bm + a_row) < TT;

    bool mval[4];
    #pragma unroll
    for (int mi = 0; mi < 4; mi++)
        mval[mi] = (bm + warp_m * 64 + mi * 16) < TT;

    float4 fa0 = make_float4(0, 0, 0, 0), fa1 = make_float4(0, 0, 0, 0);
    float4 fb0 = make_float4(0, 0, 0, 0), fb1 = make_float4(0, 0, 0, 0);
    if (arow_ok) {
        fa0 = *reinterpret_cast<const float4*>(temb + (size_t)(bm + a_row) * KEMB + a_half * 8);
        fa1 = *reinterpret_cast<const float4*>(temb + (size_t)(bm + a_row) * KEMB + a_half * 8 + 4);
    }
    if (bcol < VV) {
        fb0 = *reinterpret_cast<const float4*>(wemb + (size_t)b_row * VV + bcol);
        fb1 = *reinterpret_cast<const float4*>(wemb + (size_t)b_row * VV + bcol + 4);
    }
    {
        __nv_bfloat162 q0 = __floats2bfloat162_rn(fa0.x, fa0.y);
        __nv_bfloat162 q1 = __floats2bfloat162_rn(fa0.z, fa0.w);
        __nv_bfloat162 q2 = __floats2bfloat162_rn(fa1.x, fa1.y);
        __nv_bfloat162 q3 = __floats2bfloat162_rn(fa1.z, fa1.w);
        uint4 aa = make_uint4(*(uint32_t*)&q0, *(uint32_t*)&q1, *(uint32_t*)&q2, *(uint32_t*)&q3);
        *reinterpret_cast<uint4*>(&As[0][a_row * 24 + a_half * 8]) = aa;
        __nv_bfloat162 p0 = __floats2bfloat162_rn(fb0.x, fb0.y);
        __nv_bfloat162 p1 = __floats2bfloat162_rn(fb0.z, fb0.w);
        __nv_bfloat162 p2 = __floats2bfloat162_rn(fb1.x, fb1.y);
        __nv_bfloat162 p3 = __floats2bfloat162_rn(fb1.z, fb1.w);
        uint4 bb = make_uint4(*(uint32_t*)&p0, *(uint32_t*)&p1, *(uint32_t*)&p2, *(uint32_t*)&p3);
        *reinterpret_cast<uint4*>(&Bs[0][b_row * 136 + b_seg * 8]) = bb;
    }
    __syncthreads();

    float acc[4][4][4] = {};
    const int a_off = ((warp_m * 64 + (lane & 15)) * 24 + (lane >> 4) * 8) * 2;
    const int b_off = (((lane & 7) + ((lane >> 3) & 1) * 8) * 136 + warp_n * 32 + (lane >> 4) * 8) * 2;

    const int NK = KEMB / 16;
    for (int c = 0; c < NK; ++c) {
        if (c < NK - 1) {
            int k0 = (c + 1) * 16;
            if (arow_ok) {
                fa0 = *reinterpret_cast<const float4*>(temb + (size_t)(bm + a_row) * KEMB + k0 + a_half * 8);
                fa1 = *reinterpret_cast<const float4*>(temb + (size_t)(bm + a_row) * KEMB + k0 + a_half * 8 + 4);
            }
            if (bcol < VV) {
                fb0 = *reinterpret_cast<const float4*>(wemb + (size_t)(k0 + b_row) * VV + bcol);
                fb1 = *reinterpret_cast<const float4*>(wemb + (size_t)(k0 + b_row) * VV + bcol + 4);
            }
        }
        int cur = c & 1;
        uint32_t ab = smem_u32(&As[cur][0]) + a_off;
        uint32_t bb = smem_u32(&Bs[cur][0]) + b_off;
        uint32_t a[4][4], b[4][2];
        #pragma unroll
        for (int mi = 0; mi < 4; mi++)
            if (mval[mi])
                ldsm_x4(a[mi][0], a[mi][1], a[mi][2], a[mi][3], ab + mi * 16 * 24 * 2);
        ldsm_x4(b[0][0], b[0][1], b[1][0], b[1][1], bb);
        ldsm_x4(b[2][0], b[2][1], b[3][0], b[3][1], bb + 32);
        #pragma unroll
        for (int mi = 0; mi < 4; mi++)
            if (mval[mi])
                #pragma unroll
                for (int ni = 0; ni < 4; ni++)
                    mma_bf16(acc[mi][ni], a[mi], b[ni]);
        if (c < NK - 1) {
            int nxt = 1 - cur;
            __nv_bfloat162 q0 = __floats2bfloat162_rn(fa0.x, fa0.y);
            __nv_bfloat162 q1 = __floats2bfloat162_rn(fa0.z, fa0.w);
            __nv_bfloat162 q2 = __floats2bfloat162_rn(fa1.x, fa1.y);
            __nv_bfloat162 q3 = __floats2bfloat162_rn(fa1.z, fa1.w);
            uint4 aa = make_uint4(*(uint32_t*)&q0, *(uint32_t*)&q1, *(uint32_t*)&q2, *(uint32_t*)&q3);
            *reinterpret_cast<uint4*>(&As[nxt][a_row * 24 + a_half * 8]) = aa;
            __nv_bfloat162 p0 = __floats2bfloat162_rn(fb0.x, fb0.y);
            __nv_bfloat162 p1 = __floats2bfloat162_rn(fb0.z, fb0.w);
            __nv_bfloat162 p2 = __floats2bfloat162_rn(fb1.x, fb1.y);
            __nv_bfloat162 p3 = __floats2bfloat162_rn(fb1.z, fb1.w);
            uint4 bpk = make_uint4(*(uint32_t*)&p0, *(uint32_t*)&p1, *(uint32_t*)&p2, *(uint32_t*)&p3);
            *reinterpret_cast<uint4*>(&Bs[nxt][b_row * 136 + b_seg * 8]) = bpk;
            __syncthreads();
        }
    }

    // epilogue: e = exp(wt), store bf16
    #pragma unroll
    for (int mi = 0; mi < 4; mi++) {
        if (!mval[mi]) continue;
        int r0 = bm + warp_m * 64 + mi * 16 + (lane >> 2);
        #pragma unroll
        for (int ni = 0; ni < 4; ni++) {
            int n0 = vb + warp_n * 32 + ni * 8 + (lane & 3) * 2;
            if (n0 < VV) {
                if (r0 < TT) {
                    *reinterpret_cast<__nv_bfloat162*>(g_wtb + (size_t)r0 * VVP + n0) =
                        __floats2bfloat162_rn(exp_poly(acc[mi][ni][0]), exp_poly(acc[mi][ni][1]));
                }
                if (r0 + 8 < TT) {
                    *reinterpret_cast<__nv_bfloat162*>(g_wtb + (size_t)(r0 + 8) * VVP + n0) =
                        __floats2bfloat162_rn(exp_poly(acc[mi][ni][2]), exp_poly(acc[mi][ni][3]));
                }
            }
        }
    }
}

// ------------------------- segsum + segment top-20 (read-only on e) ------------------------
__global__ __launch_bounds__(256) void expsum_topk_seg() {
    int row = blockIdx.y, seg = blockIdx.x;
    int tid = threadIdx.x, lane = tid & 31, wid = tid >> 5;
    const __nv_bfloat16* p = g_wtb + (size_t)row * VVP + seg * SEGLEN;
    const int base = seg * SEGLEN;

    float lv[TK]; int li[TK];
    #pragma unroll
    for (int t = 0; t < TK; t++) { lv[t] = 0.f; li[t] = 0x7fffffff; }
    float ssum = 0.f;
    for (int i = tid; i < SEGLEN; i += 256) {
        float e = __bfloat162float(p[i]);
        ssum += e;
        if (e > lv[TK - 1]) {
            bool gt[TK];
            #pragma unroll
            for (int t = 0; t < TK; t++) gt[t] = (e > lv[t]);
            #pragma unroll
            for (int t = TK - 1; t >= 1; t--)
                if (gt[t - 1]) { lv[t] = lv[t - 1]; li[t] = li[t - 1]; }
            #pragma unroll
            for (int t = 0; t < TK; t++) {
                bool pl = gt[t] && (t == 0 || !gt[t - 1]);
                if (pl) { lv[t] = e; li[t] = base + i; }
            }
        }
    }
    #pragma unroll
    for (int off = 16; off > 0; off >>= 1) ssum += __shfl_xor_sync(0xffffffff, ssum, off);
    __shared__ float wsum[8];
    if (lane == 0) wsum[wid] = ssum;

    __shared__ float wv8[8][TK];
    __shared__ int   wi8[8][TK];
    unsigned long long head = makekey(lv[0], li[0]);
    for (int r = 0; r < TK; r++) {
        unsigned long long k = head;
        #pragma unroll
        for (int off = 16; off > 0; off >>= 1) {
            unsigned long long o = __shfl_xor_sync(0xffffffff, k, off);
            if (o > k) k = o;
        }
        if (head == k) {
            #pragma unroll
            for (int t = 0; t < TK - 1; t++) { lv[t] = lv[t + 1]; li[t] = li[t + 1]; }
            lv[TK - 1] = 0.f; li[TK - 1] = 0x7fffffff;
            head = makekey(lv[0], li[0]);
        }
        if (lane == 0) {
            wv8[wid][r] = __uint_as_float((unsigned)(k >> 32));
            wi8[wid][r] = (int)(0xFFFFFFFFu - (unsigned)(k & 0xFFFFFFFFu));
        }
    }
    __syncthreads();
    if (tid == 0) {
        float t = 0.f;
        #pragma unroll
        for (int i = 0; i < 8; i++) t += wsum[i];
        g_segsum[row * NSEG + seg] = t;
    }
    if (wid == 0) {
        unsigned long long ck[5];
        #pragma unroll
        for (int j = 0; j < 5; j++) {
            int q = lane * 5 + j;
            ck[j] = makekey(wv8[q / TK][q % TK], wi8[q / TK][q % TK]);
        }
        for (int r = 0; r < TK; r++) {
            unsigned long long best = 0ULL;
            #pragma unroll
            for (int j = 0; j < 5; j++) if (ck[j] > best) best = ck[j];
            unsigned long long k = best;
            #pragma unroll
            for (int off = 16; off > 0; off >>= 1) {
                unsigned long long o = __shfl_xor_sync(0xffffffff, k, off);
                if (o > k) k = o;
            }
            #pragma unroll
            for (int j = 0; j < 5; j++) if (ck[j] == k) ck[j] = 0ULL;
            if (lane == 0) {
                g_cand_v[(row * NSEG + seg) * TK + r] = __uint_as_float((unsigned)(k >> 32));
                g_cand_i[(row * NSEG + seg) * TK + r] = (int)(0xFFFFFFFFu - (unsigned)(k & 0xFFFFFFFFu));
            }
        }
    }
}

// ------------------------- merge NSEG*TK=40 candidates -> top-20, normalize, rowinv --------
__global__ void candmerge_kernel() {
    int row = blockIdx.x;
    int lane = threadIdx.x;
    unsigned long long ck[2];
    #pragma unroll
    for (int j = 0; j < 2; j++) {
        int q = lane * 2 + j;
        ck[j] = (q < NSEG * TK)
              ? makekey(g_cand_v[row * (NSEG * TK) + q], g_cand_i[row * (NSEG * TK) + q])
              : 0ULL;
    }
    float selv[TK]; int seli[TK];
    for (int r = 0; r < TK; r++) {
        unsigned long long best = 0ULL;
        #pragma unroll
        for (int j = 0; j < 2; j++) if (ck[j] > best) best = ck[j];
        unsigned long long k = best;
        #pragma unroll
        for (int off = 16; off > 0; off >>= 1) {
            unsigned long long o = __shfl_xor_sync(0xffffffff, k, off);
            if (o > k) k = o;
        }
        #pragma unroll
        for (int j = 0; j < 2; j++) if (ck[j] == k) ck[j] = 0ULL;
        selv[r] = __uint_as_float((unsigned)(k >> 32));
        seli[r] = (int)(0xFFFFFFFFu - (unsigned)(k & 0xFFFFFFFFu));
    }
    if (lane == 0) {
        float s = 0.f;
        #pragma unroll
        for (int r = 0; r < TK; r++) s += selv[r];
        float inv = 1.f / s, sq = 0.f;
        #pragma unroll
        for (int r = 0; r < TK; r++) {
            float nv = selv[r] * inv;
            g_topv[row * TK + r] = nv;
            g_topi[row * TK + r] = seli[r];
            sq += nv * nv;
        }
        g_sq[row] = sq;
        float bs = 0.f;
        #pragma unroll
        for (int s8 = 0; s8 < NSEG; s8++) bs += g_segsum[row * NSEG + s8];
        g_rowinv[row] = 1.f / bs;
    }
}

// ------------------------- theta' = theta * rowinv[t] -> bf16 padded -------------------------
__global__ void scale_theta(const float* __restrict__ theta) {
    int row = blockIdx.x;
    int t = threadIdx.x;
    if (t < TT)
        g_thb[(size_t)row * TTP + t] = __float2bfloat16(theta[row * TT + t] * g_rowinv[t]);
    else if (t < TTP)
        g_thb[(size_t)row * TTP + t] = __float2bfloat16(0.f);
}

// ------------------------- STDR via sparse gram -------------------------
__global__ void stdr_kernel(float* __restrict__ out_stdr) {
    int i = blockIdx.x;
    int tid = threadIdx.x;
    __shared__ float vi[TK]; __shared__ int ii[TK];
    __shared__ float red[256];
    if (tid < TK) { vi[tid] = g_topv[i * TK + tid]; ii[tid] = g_topi[i * TK + tid]; }
    __syncthreads();
    float part = 0.f;
    float sqi = g_sq[i];
    for (int j = tid; j < TT; j += 256) {
        float g = 0.f;
        for (int b = 0; b < TK; b++) {
            int jb = g_topi[j * TK + b];
            float vb = g_topv[j * TK + b];
            #pragma unroll
            for (int a = 0; a < TK; a++)
                if (ii[a] == jb) g += vi[a] * vb;
        }
        float d2 = sqi + g_sq[j] - 2.f * g;
        part += 0.5f * fmaxf(d2, 0.f);
    }
    red[tid] = part;
    __syncthreads();
    for (int s = 128; s > 0; s >>= 1) {
        if (tid < s) red[tid] += red[tid + s];
        __syncthreads();
    }
    if (tid == 0) atomicAdd(out_stdr, red[0] * (1.f / ((float)TT * (float)TT)));
}

// ------------------------- fused Re: 12 x k16 + 1 x k8 (no K padding waste) ----------------
// grid (391, 16), x = vocab (fast / streaming), y = bm.
#define LDA 216   // 208 + 8 pad (bf16)
#define LDB 136   // 128 + 8 pad (bf16)

__global__ __launch_bounds__(256, 2) void fused_re_mma(const float* __restrict__ dbow,
                                                       float* __restrict__ Re) {
    extern __shared__ char smraw[];
    __nv_bfloat16* As = (__nv_bfloat16*)smraw;            // 128 x LDA
    __nv_bfloat16* Bs = As + 128 * LDA;                   // 208 x LDB

    const int tid = threadIdx.x, lane = tid & 31, wid = tid >> 5;
    const int warp_m = wid >> 2, warp_n = wid & 3;
    const int bm = blockIdx.y * 128;
    const int vb = blockIdx.x * 128;

    // L2-prefetch the dbow tile (128 rows x 512B = 512 cache lines; 2 per thread).
    #pragma unroll
    for (int i = 0; i < 2; i++) {
        int l = tid * 2 + i;
        int row = l >> 2, seg = l & 3;
        int col = vb + seg * 32;
        if (col + 32 <= VV)
            prefetch_l2(dbow + (size_t)(bm + row) * VV + col);
    }

    // load full A tile (128 x 208 bf16) and B tile (208 x 128 bf16)
    #pragma unroll
    for (int i = 0; i < 13; i++) {
        int idx = tid + i * 256;
        int row = idx / 26, u = idx % 26;
        uint4 v = *reinterpret_cast<const uint4*>(g_thb + (size_t)(bm + row) * TTP + u * 8);
        *reinterpret_cast<uint4*>(As + row * LDA + u * 8) = v;
    }
    #pragma unroll
    for (int i = 0; i < 13; i++) {
        int idx = tid + i * 256;
        int k = idx >> 4, u = idx & 15;
        uint4 v = *reinterpret_cast<const uint4*>(g_wtb + (size_t)k * VVP + vb + u * 8);
        *reinterpret_cast<uint4*>(Bs + k * LDB + u * 8) = v;
    }
    __syncthreads();

    // mainloop: 12 k16 chunks + 1 k8 chunk (k 192..199; 200..207 are zero-pad anyway)
    float acc[4][4][4] = {};
    const uint32_t a_base = smem_u32(As) +
        ((warp_m * 64 + (lane & 15)) * LDA + (lane >> 4) * 8) * 2;
    const uint32_t b_base = smem_u32(Bs) +
        (((lane & 7) + ((lane >> 3) & 1) * 8) * LDB + warp_n * 32 + (lane >> 4) * 8) * 2;

    #pragma unroll
    for (int kc = 0; kc < 12; kc++) {
        uint32_t a[4][4], b[4][2];
        #pragma unroll
        for (int mi = 0; mi < 4; mi++)
            ldsm_x4(a[mi][0], a[mi][1], a[mi][2], a[mi][3],
                    a_base + mi * 16 * LDA * 2 + kc * 32);
        uint32_t bb = b_base + kc * 16 * LDB * 2;
        ldsm_x4(b[0][0], b[0][1], b[1][0], b[1][1], bb);
        ldsm_x4(b[2][0], b[2][1], b[3][0], b[3][1], bb + 32);
        #pragma unroll
        for (int mi = 0; mi < 4; mi++)
            #pragma unroll
            for (int ni = 0; ni < 4; ni++)
                mma_bf16(acc[mi][ni], a[mi], b[ni]);
    }
    {
        // final k8 chunk: lower-8 sub-fragments of the same ldsm loads
        const int kc = 12;
        uint32_t a[4][4], b[4][2];
        #pragma unroll
        for (int mi = 0; mi < 4; mi++)
            ldsm_x4(a[mi][0], a[mi][1], a[mi][2], a[mi][3],
                    a_base + mi * 16 * LDA * 2 + kc * 32);
        uint32_t bb = b_base + kc * 16 * LDB * 2;
        ldsm_x4(b[0][0], b[0][1], b[1][0], b[1][1], bb);
        ldsm_x4(b[2][0], b[2][1], b[3][0], b[3][1], bb + 32);
        #pragma unroll
        for (int mi = 0; mi < 4; mi++)
            #pragma unroll
            for (int ni = 0; ni < 4; ni++)
                mma_bf16_k8(acc[mi][ni], a[mi][0], a[mi][1], b[ni][0]);
    }
    __syncthreads();

    // epilogue: dbow (L2-warm) direct from global, -log(logit)*dbow, per-row reduce
    float* sre = (float*)As;   // reuse A region
    if (tid < 128) sre[tid] = 0.f;
    __syncthreads();

    #pragma unroll
    for (int mi = 0; mi < 4; mi++) {
        int r0 = bm + warp_m * 64 + mi * 16 + (lane >> 2);
        float p0 = 0.f, p1 = 0.f;
        #pragma unroll
        for (int ni = 0; ni < 4; ni++) {
            int n0 = vb + warp_n * 32 + ni * 8 + (lane & 3) * 2;
            if (n0 < VV) {
                float2 d0 = *reinterpret_cast<const float2*>(dbow + (size_t)r0 * VV + n0);
                float2 d1 = *reinterpret_cast<const float2*>(dbow + (size_t)(r0 + 8) * VV + n0);
                p0 -= __logf(acc[mi][ni][0]) * d0.x + __logf(acc[mi][ni][1]) * d0.y;
                p1 -= __logf(acc[mi][ni][2]) * d1.x + __logf(acc[mi][ni][3]) * d1.y;
            }
        }
        p0 += __shfl_xor_sync(0xffffffff, p0, 1);
        p0 += __shfl_xor_sync(0xffffffff, p0, 2);
        p1 += __shfl_xor_sync(0xffffffff, p1, 1);
        p1 += __shfl_xor_sync(0xffffffff, p1, 2);
        if ((lane & 3) == 0) {
            int rl = warp_m * 64 + mi * 16 + (lane >> 2);
            atomicAdd(&sre[rl], p0);
            atomicAdd(&sre[rl + 8], p1);
        }
    }
    __syncthreads();
    if (tid < 128) atomicAdd(&Re[bm + tid], sre[tid]);
}

// ------------------------- launch -------------------------
extern "C" void kernel_launch(void* const* d_in, const int* in_sizes, int n_in,
                              void* d_out, int out_size) {
    (void)in_sizes; (void)n_in; (void)out_size;
    const float* alpha = (const float*)d_in[0];
    const float* dbow  = (const float*)d_in[1];
    const float* temb  = (const float*)d_in[2];
    const float* wemb  = (const float*)d_in[3];
    float* out   = (float*)d_out;
    float* Re    = out;            // [0 .. 2047]
    float* stdr  = out + BB;       // [2048]
    float* theta = out + BB + 1;   // [2049 ...]

    cudaMemsetAsync(out, 0, (BB + 1) * sizeof(float));
    theta_kernel<<<BB, 256>>>(alpha, theta);

    wt_mma_kernel<<<dim3((VV + 127) / 128, 2), 256>>>(temb, wemb);

    expsum_topk_seg<<<dim3(NSEG, TT), 256>>>();
    candmerge_kernel<<<TT, 32>>>();
    scale_theta<<<BB, 256>>>(theta);
    stdr_kernel<<<TT, 256>>>(stdr);

    {
        size_t sm = (size_t)128 * LDA * 2 + (size_t)TTP * LDB * 2;
        cudaFuncSetAttribute(fused_re_mma,
                             cudaFuncAttributeMaxDynamicSharedMemorySize, (int)sm);
        fused_re_mma<<<dim3((VV + 127) / 128, BB / 128), 256, sm>>>(dbow, Re);
    }
}

// round 16
// speedup vs baseline: 1.4843x; 1.4843x over previous
#include <cuda_runtime.h>
#include <cuda_bf16.h>
#include <cstdint>

#define VV 50000
#define VVP 50048            // padded vocab
#define TT 200
#define TTP 208              // padded topic dim (13*16)
#define KEMB 512
#define BB 2048
#define TK 20
#define NSEG 2
#define SEGLEN 25000

// ------------------------- static device scratch -------------------------
// g_wtb holds e = exp(wt) in bf16 (written directly by wt_mma's epilogue; no max shift
// needed since |wt| <= ~0.35). Padding rows/cols stay zero from static init.
__device__ __align__(16) __nv_bfloat16 g_wtb[(size_t)TTP * VVP];
__device__ __align__(16) __nv_bfloat16 g_ta[256 * KEMB];        // topic_emb bf16 padded rows
__device__ __align__(16) __nv_bfloat16 g_thb[(size_t)BB * TTP]; // theta' = theta * rowinv[t]
__device__ __align__(16) float g_segsum[TT * NSEG];
__device__ __align__(16) float g_cand_v[TT * NSEG * TK];
__device__ __align__(16) int   g_cand_i[TT * NSEG * TK];
__device__ __align__(16) float g_topv[TT * TK];
__device__ __align__(16) int   g_topi[TT * TK];
__device__ __align__(16) float g_sq[TT];
__device__ __align__(16) float g_rowinv[TT];

// ------------------------- helpers -------------------------
__device__ __forceinline__ uint32_t smem_u32(const void* p) {
    return (uint32_t)__cvta_generic_to_shared(p);
}
__device__ __forceinline__ void ldsm_x4(uint32_t& r0, uint32_t& r1, uint32_t& r2, uint32_t& r3,
                                        uint32_t addr) {
    asm volatile("ldmatrix.sync.aligned.m8n8.x4.shared.b16 {%0,%1,%2,%3}, [%4];\n"
                 : "=r"(r0), "=r"(r1), "=r"(r2), "=r"(r3) : "r"(addr));
}
__device__ __forceinline__ void mma_bf16(float* d, const uint32_t* a, const uint32_t* b) {
    asm volatile(
        "mma.sync.aligned.m16n8k16.row.col.f32.bf16.bf16.f32 "
        "{%0,%1,%2,%3},{%4,%5,%6,%7},{%8,%9},{%0,%1,%2,%3};\n"
        : "+f"(d[0]), "+f"(d[1]), "+f"(d[2]), "+f"(d[3])
        : "r"(a[0]), "r"(a[1]), "r"(a[2]), "r"(a[3]), "r"(b[0]), "r"(b[1]));
}
__device__ __forceinline__ void prefetch_l2(const void* p) {
    asm volatile("prefetch.global.L2 [%0];\n" :: "l"(p));
}
// exp(x) for |x| <= ~0.4: degree-8 Taylor/Horner on the FMA pipe. abs err < 3e-10.
__device__ __forceinline__ float exp_poly(float x) {
    float r = 2.4801587e-5f;
    r = fmaf(r, x, 1.9841270e-4f);
    r = fmaf(r, x, 1.3888889e-3f);
    r = fmaf(r, x, 8.3333333e-3f);
    r = fmaf(r, x, 4.1666667e-2f);
    r = fmaf(r, x, 1.6666667e-1f);
    r = fmaf(r, x, 0.5f);
    r = fmaf(r, x, 1.0f);
    r = fmaf(r, x, 1.0f);
    return r;
}
__device__ __forceinline__ unsigned long long makekey(float v, int i) {
    // valid for v >= 0
    return ((unsigned long long)__float_as_uint(v) << 32) |
           (unsigned long long)(0xFFFFFFFFu - (unsigned)i);
}

// ------------------------- theta = softmax(alpha) -------------------------
__global__ void theta_kernel(const float* __restrict__ alpha, float* __restrict__ theta) {
    int row = blockIdx.x;
    int tid = threadIdx.x;
    __shared__ float red[256];
    float x = (tid < TT) ? alpha[row * TT + tid] : -1e30f;
    red[tid] = x;
    __syncthreads();
    for (int s = 128; s > 0; s >>= 1) {
        if (tid < s) red[tid] = fmaxf(red[tid], red[tid + s]);
        __syncthreads();
    }
    float m = red[0];
    __syncthreads();
    float e = (tid < TT) ? __expf(x - m) : 0.f;
    red[tid] = e;
    __syncthreads();
    for (int s = 128; s > 0; s >>= 1) {
        if (tid < s) red[tid] += red[tid + s];
        __syncthreads();
    }
    float inv = 1.f / red[0];
    if (tid < TT) theta[row * TT + tid] = e * inv;
}

// ------------------------- topic_emb -> bf16 (padded to 256 rows) -------------------------
__global__ void conv_ta(const float* __restrict__ temb) {
    int i = blockIdx.x * 256 + threadIdx.x;
    if (i < 256 * KEMB) {
        int r = i >> 9, c = i & 511;
        float v = (r < TT) ? temb[r * KEMB + c] : 0.f;
        g_ta[i] = __float2bfloat16(v);
    }
}

// ------------------------- wt_mma: e = exp(topic_emb @ word_emb), bf16 out ----------------
// grid ((VV+127)/128, 2), x = vocab (fast / streaming), y = bm.
// No max subtraction: |wt| <= ~0.35, exp is fp32-safe. exp_poly runs on the idle FMA pipe.
__global__ __launch_bounds__(256, 2) void wt_mma_kernel(const float* __restrict__ wemb) {
    __shared__ __align__(16) __nv_bfloat16 As[2][128 * 24];
    __shared__ __align__(16) __nv_bfloat16 Bs[2][16 * 136];
    const int tid = threadIdx.x, lane = tid & 31, wid = tid >> 5;
    const int warp_m = wid >> 2, warp_n = wid & 3;
    const int bm = blockIdx.y * 128, vb = blockIdx.x * 128;
    const int a_row = tid >> 1, a_half = tid & 1;
    const int b_row = tid >> 4, b_seg = tid & 15;
    const int bcol = vb + b_seg * 8;

    bool mval[4];
    #pragma unroll
    for (int mi = 0; mi < 4; mi++)
        mval[mi] = (bm + warp_m * 64 + mi * 16) < TT;

    uint4 ra = *reinterpret_cast<const uint4*>(g_ta + (size_t)(bm + a_row) * KEMB + a_half * 8);
    float4 fb0 = make_float4(0, 0, 0, 0), fb1 = make_float4(0, 0, 0, 0);
    if (bcol < VV) {
        fb0 = *reinterpret_cast<const float4*>(wemb + (size_t)b_row * VV + bcol);
        fb1 = *reinterpret_cast<const float4*>(wemb + (size_t)b_row * VV + bcol + 4);
    }
    *reinterpret_cast<uint4*>(&As[0][a_row * 24 + a_half * 8]) = ra;
    {
        __nv_bfloat162 p0 = __floats2bfloat162_rn(fb0.x, fb0.y);
        __nv_bfloat162 p1 = __floats2bfloat162_rn(fb0.z, fb0.w);
        __nv_bfloat162 p2 = __floats2bfloat162_rn(fb1.x, fb1.y);
        __nv_bfloat162 p3 = __floats2bfloat162_rn(fb1.z, fb1.w);
        uint4 bb = make_uint4(*(uint32_t*)&p0, *(uint32_t*)&p1, *(uint32_t*)&p2, *(uint32_t*)&p3);
        *reinterpret_cast<uint4*>(&Bs[0][b_row * 136 + b_seg * 8]) = bb;
    }
    __syncthreads();

    float acc[4][4][4] = {};
    const int a_off = ((warp_m * 64 + (lane & 15)) * 24 + (lane >> 4) * 8) * 2;
    const int b_off = (((lane & 7) + ((lane >> 3) & 1) * 8) * 136 + warp_n * 32 + (lane >> 4) * 8) * 2;

    const int NK = KEMB / 16;
    for (int c = 0; c < NK; ++c) {
        if (c < NK - 1) {
            int k0 = (c + 1) * 16;
            ra = *reinterpret_cast<const uint4*>(g_ta + (size_t)(bm + a_row) * KEMB + k0 + a_half * 8);
            if (bcol < VV) {
                fb0 = *reinterpret_cast<const float4*>(wemb + (size_t)(k0 + b_row) * VV + bcol);
                fb1 = *reinterpret_cast<const float4*>(wemb + (size_t)(k0 + b_row) * VV + bcol + 4);
            }
        }
        int cur = c & 1;
        uint32_t ab = smem_u32(&As[cur][0]) + a_off;
        uint32_t bb = smem_u32(&Bs[cur][0]) + b_off;
        uint32_t a[4][4], b[4][2];
        #pragma unroll
        for (int mi = 0; mi < 4; mi++)
            if (mval[mi])
                ldsm_x4(a[mi][0], a[mi][1], a[mi][2], a[mi][3], ab + mi * 16 * 24 * 2);
        ldsm_x4(b[0][0], b[0][1], b[1][0], b[1][1], bb);
        ldsm_x4(b[2][0], b[2][1], b[3][0], b[3][1], bb + 32);
        #pragma unroll
        for (int mi = 0; mi < 4; mi++)
            if (mval[mi])
                #pragma unroll
                for (int ni = 0; ni < 4; ni++)
                    mma_bf16(acc[mi][ni], a[mi], b[ni]);
        if (c < NK - 1) {
            int nxt = 1 - cur;
            *reinterpret_cast<uint4*>(&As[nxt][a_row * 24 + a_half * 8]) = ra;
            __nv_bfloat162 p0 = __floats2bfloat162_rn(fb0.x, fb0.y);
            __nv_bfloat162 p1 = __floats2bfloat162_rn(fb0.z, fb0.w);
            __nv_bfloat162 p2 = __floats2bfloat162_rn(fb1.x, fb1.y);
            __nv_bfloat162 p3 = __floats2bfloat162_rn(fb1.z, fb1.w);
            uint4 bpk = make_uint4(*(uint32_t*)&p0, *(uint32_t*)&p1, *(uint32_t*)&p2, *(uint32_t*)&p3);
            *reinterpret_cast<uint4*>(&Bs[nxt][b_row * 136 + b_seg * 8]) = bpk;
            __syncthreads();
        }
    }

    // epilogue: e = exp(wt), store bf16
    #pragma unroll
    for (int mi = 0; mi < 4; mi++) {
        if (!mval[mi]) continue;
        int r0 = bm + warp_m * 64 + mi * 16 + (lane >> 2);
        #pragma unroll
        for (int ni = 0; ni < 4; ni++) {
            int n0 = vb + warp_n * 32 + ni * 8 + (lane & 3) * 2;
            if (n0 < VV) {
                if (r0 < TT) {
                    *reinterpret_cast<__nv_bfloat162*>(g_wtb + (size_t)r0 * VVP + n0) =
                        __floats2bfloat162_rn(exp_poly(acc[mi][ni][0]), exp_poly(acc[mi][ni][1]));
                }
                if (r0 + 8 < TT) {
                    *reinterpret_cast<__nv_bfloat162*>(g_wtb + (size_t)(r0 + 8) * VVP + n0) =
                        __floats2bfloat162_rn(exp_poly(acc[mi][ni][2]), exp_poly(acc[mi][ni][3]));
                }
            }
        }
    }
}

// ------------------------- segsum + segment top-20 (read-only on e) ------------------------
__global__ __launch_bounds__(256) void expsum_topk_seg() {
    int row = blockIdx.y, seg = blockIdx.x;
    int tid = threadIdx.x, lane = tid & 31, wid = tid >> 5;
    const __nv_bfloat16* p = g_wtb + (size_t)row * VVP + seg * SEGLEN;
    const int base = seg * SEGLEN;

    float lv[TK]; int li[TK];
    #pragma unroll
    for (int t = 0; t < TK; t++) { lv[t] = 0.f; li[t] = 0x7fffffff; }
    float ssum = 0.f;
    for (int i = tid; i < SEGLEN; i += 256) {
        float e = __bfloat162float(p[i]);
        ssum += e;
        if (e > lv[TK - 1]) {
            bool gt[TK];
            #pragma unroll
            for (int t = 0; t < TK; t++) gt[t] = (e > lv[t]);
            #pragma unroll
            for (int t = TK - 1; t >= 1; t--)
                if (gt[t - 1]) { lv[t] = lv[t - 1]; li[t] = li[t - 1]; }
            #pragma unroll
            for (int t = 0; t < TK; t++) {
                bool pl = gt[t] && (t == 0 || !gt[t - 1]);
                if (pl) { lv[t] = e; li[t] = base + i; }
            }
        }
    }
    #pragma unroll
    for (int off = 16; off > 0; off >>= 1) ssum += __shfl_xor_sync(0xffffffff, ssum, off);
    __shared__ float wsum[8];
    if (lane == 0) wsum[wid] = ssum;

    __shared__ float wv8[8][TK];
    __shared__ int   wi8[8][TK];
    unsigned long long head = makekey(lv[0], li[0]);
    for (int r = 0; r < TK; r++) {
        unsigned long long k = head;
        #pragma unroll
        for (int off = 16; off > 0; off >>= 1) {
            unsigned long long o = __shfl_xor_sync(0xffffffff, k, off);
            if (o > k) k = o;
        }
        if (head == k) {
            #pragma unroll
            for (int t = 0; t < TK - 1; t++) { lv[t] = lv[t + 1]; li[t] = li[t + 1]; }
            lv[TK - 1] = 0.f; li[TK - 1] = 0x7fffffff;
            head = makekey(lv[0], li[0]);
        }
        if (lane == 0) {
            wv8[wid][r] = __uint_as_float((unsigned)(k >> 32));
            wi8[wid][r] = (int)(0xFFFFFFFFu - (unsigned)(k & 0xFFFFFFFFu));
        }
    }
    __syncthreads();
    if (tid == 0) {
        float t = 0.f;
        #pragma unroll
        for (int i = 0; i < 8; i++) t += wsum[i];
        g_segsum[row * NSEG + seg] = t;
    }
    if (wid == 0) {
        unsigned long long ck[5];
        #pragma unroll
        for (int j = 0; j < 5; j++) {
            int q = lane * 5 + j;
            ck[j] = makekey(wv8[q / TK][q % TK], wi8[q / TK][q % TK]);
        }
        for (int r = 0; r < TK; r++) {
            unsigned long long best = 0ULL;
            #pragma unroll
            for (int j = 0; j < 5; j++) if (ck[j] > best) best = ck[j];
            unsigned long long k = best;
            #pragma unroll
            for (int off = 16; off > 0; off >>= 1) {
                unsigned long long o = __shfl_xor_sync(0xffffffff, k, off);
                if (o > k) k = o;
            }
            #pragma unroll
            for (int j = 0; j < 5; j++) if (ck[j] == k) ck[j] = 0ULL;
            if (lane == 0) {
                g_cand_v[(row * NSEG + seg) * TK + r] = __uint_as_float((unsigned)(k >> 32));
                g_cand_i[(row * NSEG + seg) * TK + r] = (int)(0xFFFFFFFFu - (unsigned)(k & 0xFFFFFFFFu));
            }
        }
    }
}

// ------------------------- merge NSEG*TK=40 candidates -> top-20, normalize, rowinv --------
__global__ void candmerge_kernel() {
    int row = blockIdx.x;
    int lane = threadIdx.x;
    unsigned long long ck[2];
    #pragma unroll
    for (int j = 0; j < 2; j++) {
        int q = lane * 2 + j;
        ck[j] = (q < NSEG * TK)
              ? makekey(g_cand_v[row * (NSEG * TK) + q], g_cand_i[row * (NSEG * TK) + q])
              : 0ULL;
    }
    float selv[TK]; int seli[TK];
    for (int r = 0; r < TK; r++) {
        unsigned long long best = 0ULL;
        #pragma unroll
        for (int j = 0; j < 2; j++) if (ck[j] > best) best = ck[j];
        unsigned long long k = best;
        #pragma unroll
        for (int off = 16; off > 0; off >>= 1) {
            unsigned long long o = __shfl_xor_sync(0xffffffff, k, off);
            if (o > k) k = o;
        }
        #pragma unroll
        for (int j = 0; j < 2; j++) if (ck[j] == k) ck[j] = 0ULL;
        selv[r] = __uint_as_float((unsigned)(k >> 32));
        seli[r] = (int)(0xFFFFFFFFu - (unsigned)(k & 0xFFFFFFFFu));
    }
    if (lane == 0) {
        float s = 0.f;
        #pragma unroll
        for (int r = 0; r < TK; r++) s += selv[r];
        float inv = 1.f / s, sq = 0.f;
        #pragma unroll
        for (int r = 0; r < TK; r++) {
            float nv = selv[r] * inv;
            g_topv[row * TK + r] = nv;
            g_topi[row * TK + r] = seli[r];
            sq += nv * nv;
        }
        g_sq[row] = sq;
        float bs = 0.f;
        #pragma unroll
        for (int s8 = 0; s8 < NSEG; s8++) bs += g_segsum[row * NSEG + s8];
        g_rowinv[row] = 1.f / bs;
    }
}

// ------------------------- theta' = theta * rowinv[t] -> bf16 padded -------------------------
__global__ void scale_theta(const float* __restrict__ theta) {
    int row = blockIdx.x;
    int t = threadIdx.x;
    if (t < TT)
        g_thb[(size_t)row * TTP + t] = __float2bfloat16(theta[row * TT + t] * g_rowinv[t]);
    else if (t < TTP)
        g_thb[(size_t)row * TTP + t] = __float2bfloat16(0.f);
}

// ------------------------- STDR via sparse gram -------------------------
__global__ void stdr_kernel(float* __restrict__ out_stdr) {
    int i = blockIdx.x;
    int tid = threadIdx.x;
    __shared__ float vi[TK]; __shared__ int ii[TK];
    __shared__ float red[256];
    if (tid < TK) { vi[tid] = g_topv[i * TK + tid]; ii[tid] = g_topi[i * TK + tid]; }
    __syncthreads();
    float part = 0.f;
    float sqi = g_sq[i];
    for (int j = tid; j < TT; j += 256) {
        float g = 0.f;
        for (int b = 0; b < TK; b++) {
            int jb = g_topi[j * TK + b];
            float vb = g_topv[j * TK + b];
            #pragma unroll
            for (int a = 0; a < TK; a++)
                if (ii[a] == jb) g += vi[a] * vb;
        }
        float d2 = sqi + g_sq[j] - 2.f * g;
        part += 0.5f * fmaxf(d2, 0.f);
    }
    red[tid] = part;
    __syncthreads();
    for (int s = 128; s > 0; s >>= 1) {
        if (tid < s) red[tid] += red[tid + s];
        __syncthreads();
    }
    if (tid == 0) atomicAdd(out_stdr, red[0] * (1.f / ((float)TT * (float)TT)));
}

// ------------------------- fused Re: full-K smem, L2-prefetched dbow epilogue -------------
// grid (391, 16), x = vocab (fast / streaming), y = bm.  (R14 config: 13 uniform k16 chunks)
#define LDA 216   // 208 + 8 pad (bf16)
#define LDB 136   // 128 + 8 pad (bf16)

__global__ __launch_bounds__(256, 2) void fused_re_mma(const float* __restrict__ dbow,
                                                       float* __restrict__ Re) {
    extern __shared__ char smraw[];
    __nv_bfloat16* As = (__nv_bfloat16*)smraw;            // 128 x LDA
    __nv_bfloat16* Bs = As + 128 * LDA;                   // 208 x LDB

    const int tid = threadIdx.x, lane = tid & 31, wid = tid >> 5;
    const int warp_m = wid >> 2, warp_n = wid & 3;
    const int bm = blockIdx.y * 128;
    const int vb = blockIdx.x * 128;

    // L2-prefetch the dbow tile (128 rows x 512B = 512 cache lines; 2 per thread).
    #pragma unroll
    for (int i = 0; i < 2; i++) {
        int l = tid * 2 + i;
        int row = l >> 2, seg = l & 3;
        int col = vb + seg * 32;
        if (col + 32 <= VV)
            prefetch_l2(dbow + (size_t)(bm + row) * VV + col);
    }

    // load full A tile (128 x 208 bf16) and B tile (208 x 128 bf16)
    #pragma unroll
    for (int i = 0; i < 13; i++) {
        int idx = tid + i * 256;
        int row = idx / 26, u = idx % 26;
        uint4 v = *reinterpret_cast<const uint4*>(g_thb + (size_t)(bm + row) * TTP + u * 8);
        *reinterpret_cast<uint4*>(As + row * LDA + u * 8) = v;
    }
    #pragma unroll
    for (int i = 0; i < 13; i++) {
        int idx = tid + i * 256;
        int k = idx >> 4, u = idx & 15;
        uint4 v = *reinterpret_cast<const uint4*>(g_wtb + (size_t)k * VVP + vb + u * 8);
        *reinterpret_cast<uint4*>(Bs + k * LDB + u * 8) = v;
    }
    __syncthreads();

    // mainloop: 13 uniform k16 chunks, pure smem
    float acc[4][4][4] = {};
    const uint32_t a_base = smem_u32(As) +
        ((warp_m * 64 + (lane & 15)) * LDA + (lane >> 4) * 8) * 2;
    const uint32_t b_base = smem_u32(Bs) +
        (((lane & 7) + ((lane >> 3) & 1) * 8) * LDB + warp_n * 32 + (lane >> 4) * 8) * 2;

    #pragma unroll
    for (int kc = 0; kc < 13; kc++) {
        uint32_t a[4][4], b[4][2];
        #pragma unroll
        for (int mi = 0; mi < 4; mi++)
            ldsm_x4(a[mi][0], a[mi][1], a[mi][2], a[mi][3],
                    a_base + mi * 16 * LDA * 2 + kc * 32);
        uint32_t bb = b_base + kc * 16 * LDB * 2;
        ldsm_x4(b[0][0], b[0][1], b[1][0], b[1][1], bb);
        ldsm_x4(b[2][0], b[2][1], b[3][0], b[3][1], bb + 32);
        #pragma unroll
        for (int mi = 0; mi < 4; mi++)
            #pragma unroll
            for (int ni = 0; ni < 4; ni++)
                mma_bf16(acc[mi][ni], a[mi], b[ni]);
    }
    __syncthreads();

    // epilogue: dbow (L2-warm) direct from global, -log(logit)*dbow, per-row reduce
    float* sre = (float*)As;   // reuse A region
    if (tid < 128) sre[tid] = 0.f;
    __syncthreads();

    #pragma unroll
    for (int mi = 0; mi < 4; mi++) {
        int r0 = bm + warp_m * 64 + mi * 16 + (lane >> 2);
        float p0 = 0.f, p1 = 0.f;
        #pragma unroll
        for (int ni = 0; ni < 4; ni++) {
            int n0 = vb + warp_n * 32 + ni * 8 + (lane & 3) * 2;
            if (n0 < VV) {
                float2 d0 = *reinterpret_cast<const float2*>(dbow + (size_t)r0 * VV + n0);
                float2 d1 = *reinterpret_cast<const float2*>(dbow + (size_t)(r0 + 8) * VV + n0);
                p0 -= __logf(acc[mi][ni][0]) * d0.x + __logf(acc[mi][ni][1]) * d0.y;
                p1 -= __logf(acc[mi][ni][2]) * d1.x + __logf(acc[mi][ni][3]) * d1.y;
            }
        }
        p0 += __shfl_xor_sync(0xffffffff, p0, 1);
        p0 += __shfl_xor_sync(0xffffffff, p0, 2);
        p1 += __shfl_xor_sync(0xffffffff, p1, 1);
        p1 += __shfl_xor_sync(0xffffffff, p1, 2);
        if ((lane & 3) == 0) {
            int rl = warp_m * 64 + mi * 16 + (lane >> 2);
            atomicAdd(&sre[rl], p0);
            atomicAdd(&sre[rl + 8], p1);
        }
    }
    __syncthreads();
    if (tid < 128) atomicAdd(&Re[bm + tid], sre[tid]);
}

// ------------------------- launch -------------------------
extern "C" void kernel_launch(void* const* d_in, const int* in_sizes, int n_in,
                              void* d_out, int out_size) {
    (void)in_sizes; (void)n_in; (void)out_size;
    const float* alpha = (const float*)d_in[0];
    const float* dbow  = (const float*)d_in[1];
    const float* temb  = (const float*)d_in[2];
    const float* wemb  = (const float*)d_in[3];
    float* out   = (float*)d_out;
    float* Re    = out;            // [0 .. 2047]
    float* stdr  = out + BB;       // [2048]
    float* theta = out + BB + 1;   // [2049 ...]

    cudaMemsetAsync(out, 0, (BB + 1) * sizeof(float));
    theta_kernel<<<BB, 256>>>(alpha, theta);
    conv_ta<<<(256 * KEMB + 255) / 256, 256>>>(temb);

    wt_mma_kernel<<<dim3((VV + 127) / 128, 2), 256>>>(wemb);

    expsum_topk_seg<<<dim3(NSEG, TT), 256>>>();
    candmerge_kernel<<<TT, 32>>>();
    scale_theta<<<BB, 256>>>(theta);
    stdr_kernel<<<TT, 256>>>(stdr);

    {
        size_t sm = (size_t)128 * LDA * 2 + (size_t)TTP * LDB * 2;
        cudaFuncSetAttribute(fused_re_mma,
                             cudaFuncAttributeMaxDynamicSharedMemorySize, (int)sm);
        fused_re_mma<<<dim3((VV + 127) / 128, BB / 128), 256, sm>>>(dbow, Re);
    }
}

// round 17
// speedup vs baseline: 1.5051x; 1.0140x over previous
#include <cuda_runtime.h>
#include <cuda_bf16.h>
#include <cstdint>

#define VV 50000
#define VVP 50048            // padded vocab
#define TT 200
#define TTP 208              // padded topic dim (13*16)
#define KEMB 512
#define BB 2048
#define TK 20
#define NSEG 4
#define SEGLEN 12512         // VVP/4, divisible by 8
#define NCHUNK (SEGLEN / 8)  // 1564 uint4 chunks per segment

// ------------------------- static device scratch -------------------------
// g_wtb holds e = exp(wt) in bf16 (written directly by wt_mma's epilogue; no max shift
// needed since |wt| <= ~0.35). Padding rows/cols stay zero from static init.
__device__ __align__(16) __nv_bfloat16 g_wtb[(size_t)TTP * VVP];
__device__ __align__(16) __nv_bfloat16 g_ta[256 * KEMB];        // topic_emb bf16 padded rows
__device__ __align__(16) __nv_bfloat16 g_thb[(size_t)BB * TTP]; // theta' = theta * rowinv[t]
__device__ __align__(16) float g_segsum[TT * NSEG];
__device__ __align__(16) float g_cand_v[TT * NSEG * TK];
__device__ __align__(16) int   g_cand_i[TT * NSEG * TK];
__device__ __align__(16) float g_topv[TT * TK];
__device__ __align__(16) int   g_topi[TT * TK];
__device__ __align__(16) float g_sq[TT];
__device__ __align__(16) float g_rowinv[TT];

// ------------------------- helpers -------------------------
__device__ __forceinline__ uint32_t smem_u32(const void* p) {
    return (uint32_t)__cvta_generic_to_shared(p);
}
__device__ __forceinline__ void ldsm_x4(uint32_t& r0, uint32_t& r1, uint32_t& r2, uint32_t& r3,
                                        uint32_t addr) {
    asm volatile("ldmatrix.sync.aligned.m8n8.x4.shared.b16 {%0,%1,%2,%3}, [%4];\n"
                 : "=r"(r0), "=r"(r1), "=r"(r2), "=r"(r3) : "r"(addr));
}
__device__ __forceinline__ void mma_bf16(float* d, const uint32_t* a, const uint32_t* b) {
    asm volatile(
        "mma.sync.aligned.m16n8k16.row.col.f32.bf16.bf16.f32 "
        "{%0,%1,%2,%3},{%4,%5,%6,%7},{%8,%9},{%0,%1,%2,%3};\n"
        : "+f"(d[0]), "+f"(d[1]), "+f"(d[2]), "+f"(d[3])
        : "r"(a[0]), "r"(a[1]), "r"(a[2]), "r"(a[3]), "r"(b[0]), "r"(b[1]));
}
__device__ __forceinline__ void prefetch_l2(const void* p) {
    asm volatile("prefetch.global.L2 [%0];\n" :: "l"(p));
}
// exp(x) for |x| <= ~0.4: degree-8 Taylor/Horner on the FMA pipe. abs err < 3e-10.
__device__ __forceinline__ float exp_poly(float x) {
    float r = 2.4801587e-5f;
    r = fmaf(r, x, 1.9841270e-4f);
    r = fmaf(r, x, 1.3888889e-3f);
    r = fmaf(r, x, 8.3333333e-3f);
    r = fmaf(r, x, 4.1666667e-2f);
    r = fmaf(r, x, 1.6666667e-1f);
    r = fmaf(r, x, 0.5f);
    r = fmaf(r, x, 1.0f);
    r = fmaf(r, x, 1.0f);
    return r;
}
__device__ __forceinline__ unsigned long long makekey(float v, int i) {
    // valid for v >= 0
    return ((unsigned long long)__float_as_uint(v) << 32) |
           (unsigned long long)(0xFFFFFFFFu - (unsigned)i);
}

// ------------------------- theta = softmax(alpha) -------------------------
__global__ void theta_kernel(const float* __restrict__ alpha, float* __restrict__ theta) {
    int row = blockIdx.x;
    int tid = threadIdx.x;
    __shared__ float red[256];
    float x = (tid < TT) ? alpha[row * TT + tid] : -1e30f;
    red[tid] = x;
    __syncthreads();
    for (int s = 128; s > 0; s >>= 1) {
        if (tid < s) red[tid] = fmaxf(red[tid], red[tid + s]);
        __syncthreads();
    }
    float m = red[0];
    __syncthreads();
    float e = (tid < TT) ? __expf(x - m) : 0.f;
    red[tid] = e;
    __syncthreads();
    for (int s = 128; s > 0; s >>= 1) {
        if (tid < s) red[tid] += red[tid + s];
        __syncthreads();
    }
    float inv = 1.f / red[0];
    if (tid < TT) theta[row * TT + tid] = e * inv;
}

// ------------------------- topic_emb -> bf16 (padded to 256 rows) -------------------------
__global__ void conv_ta(const float* __restrict__ temb) {
    int i = blockIdx.x * 256 + threadIdx.x;
    if (i < 256 * KEMB) {
        int r = i >> 9, c = i & 511;
        float v = (r < TT) ? temb[r * KEMB + c] : 0.f;
        g_ta[i] = __float2bfloat16(v);
    }
}

// ------------------------- wt_mma: e = exp(topic_emb @ word_emb), bf16 out ----------------
// grid ((VV+127)/128, 2), x = vocab (fast / streaming), y = bm.
__global__ __launch_bounds__(256, 2) void wt_mma_kernel(const float* __restrict__ wemb) {
    __shared__ __align__(16) __nv_bfloat16 As[2][128 * 24];
    __shared__ __align__(16) __nv_bfloat16 Bs[2][16 * 136];
    const int tid = threadIdx.x, lane = tid & 31, wid = tid >> 5;
    const int warp_m = wid >> 2, warp_n = wid & 3;
    const int bm = blockIdx.y * 128, vb = blockIdx.x * 128;
    const int a_row = tid >> 1, a_half = tid & 1;
    const int b_row = tid >> 4, b_seg = tid & 15;
    const int bcol = vb + b_seg * 8;

    bool mval[4];
    #pragma unroll
    for (int mi = 0; mi < 4; mi++)
        mval[mi] = (bm + warp_m * 64 + mi * 16) < TT;

    uint4 ra = *reinterpret_cast<const uint4*>(g_ta + (size_t)(bm + a_row) * KEMB + a_half * 8);
    float4 fb0 = make_float4(0, 0, 0, 0), fb1 = make_float4(0, 0, 0, 0);
    if (bcol < VV) {
        fb0 = *reinterpret_cast<const float4*>(wemb + (size_t)b_row * VV + bcol);
        fb1 = *reinterpret_cast<const float4*>(wemb + (size_t)b_row * VV + bcol + 4);
    }
    *reinterpret_cast<uint4*>(&As[0][a_row * 24 + a_half * 8]) = ra;
    {
        __nv_bfloat162 p0 = __floats2bfloat162_rn(fb0.x, fb0.y);
        __nv_bfloat162 p1 = __floats2bfloat162_rn(fb0.z, fb0.w);
        __nv_bfloat162 p2 = __floats2bfloat162_rn(fb1.x, fb1.y);
        __nv_bfloat162 p3 = __floats2bfloat162_rn(fb1.z, fb1.w);
        uint4 bb = make_uint4(*(uint32_t*)&p0, *(uint32_t*)&p1, *(uint32_t*)&p2, *(uint32_t*)&p3);
        *reinterpret_cast<uint4*>(&Bs[0][b_row * 136 + b_seg * 8]) = bb;
    }
    __syncthreads();

    float acc[4][4][4] = {};
    const int a_off = ((warp_m * 64 + (lane & 15)) * 24 + (lane >> 4) * 8) * 2;
    const int b_off = (((lane & 7) + ((lane >> 3) & 1) * 8) * 136 + warp_n * 32 + (lane >> 4) * 8) * 2;

    const int NK = KEMB / 16;
    for (int c = 0; c < NK; ++c) {
        if (c < NK - 1) {
            int k0 = (c + 1) * 16;
            ra = *reinterpret_cast<const uint4*>(g_ta + (size_t)(bm + a_row) * KEMB + k0 + a_half * 8);
            if (bcol < VV) {
                fb0 = *reinterpret_cast<const float4*>(wemb + (size_t)(k0 + b_row) * VV + bcol);
                fb1 = *reinterpret_cast<const float4*>(wemb + (size_t)(k0 + b_row) * VV + bcol + 4);
            }
        }
        int cur = c & 1;
        uint32_t ab = smem_u32(&As[cur][0]) + a_off;
        uint32_t bb = smem_u32(&Bs[cur][0]) + b_off;
        uint32_t a[4][4], b[4][2];
        #pragma unroll
        for (int mi = 0; mi < 4; mi++)
            if (mval[mi])
                ldsm_x4(a[mi][0], a[mi][1], a[mi][2], a[mi][3], ab + mi * 16 * 24 * 2);
        ldsm_x4(b[0][0], b[0][1], b[1][0], b[1][1], bb);
        ldsm_x4(b[2][0], b[2][1], b[3][0], b[3][1], bb + 32);
        #pragma unroll
        for (int mi = 0; mi < 4; mi++)
            if (mval[mi])
                #pragma unroll
                for (int ni = 0; ni < 4; ni++)
                    mma_bf16(acc[mi][ni], a[mi], b[ni]);
        if (c < NK - 1) {
            int nxt = 1 - cur;
            *reinterpret_cast<uint4*>(&As[nxt][a_row * 24 + a_half * 8]) = ra;
            __nv_bfloat162 p0 = __floats2bfloat162_rn(fb0.x, fb0.y);
            __nv_bfloat162 p1 = __floats2bfloat162_rn(fb0.z, fb0.w);
            __nv_bfloat162 p2 = __floats2bfloat162_rn(fb1.x, fb1.y);
            __nv_bfloat162 p3 = __floats2bfloat162_rn(fb1.z, fb1.w);
            uint4 bpk = make_uint4(*(uint32_t*)&p0, *(uint32_t*)&p1, *(uint32_t*)&p2, *(uint32_t*)&p3);
            *reinterpret_cast<uint4*>(&Bs[nxt][b_row * 136 + b_seg * 8]) = bpk;
            __syncthreads();
        }
    }

    // epilogue: e = exp(wt), store bf16
    #pragma unroll
    for (int mi = 0; mi < 4; mi++) {
        if (!mval[mi]) continue;
        int r0 = bm + warp_m * 64 + mi * 16 + (lane >> 2);
        #pragma unroll
        for (int ni = 0; ni < 4; ni++) {
            int n0 = vb + warp_n * 32 + ni * 8 + (lane & 3) * 2;
            if (n0 < VV) {
                if (r0 < TT) {
                    *reinterpret_cast<__nv_bfloat162*>(g_wtb + (size_t)r0 * VVP + n0) =
                        __floats2bfloat162_rn(exp_poly(acc[mi][ni][0]), exp_poly(acc[mi][ni][1]));
                }
                if (r0 + 8 < TT) {
                    *reinterpret_cast<__nv_bfloat162*>(g_wtb + (size_t)(r0 + 8) * VVP + n0) =
                        __floats2bfloat162_rn(exp_poly(acc[mi][ni][2]), exp_poly(acc[mi][ni][3]));
                }
            }
        }
    }
}

// ------------------------- segsum + segment top-20 (vectorized, int fast-path) -------------
// grid (NSEG, TT). Segments cover VVP (padding e=0 never selected, adds 0 to sum).
__global__ __launch_bounds__(256) void expsum_topk_seg() {
    int row = blockIdx.y, seg = blockIdx.x;
    int tid = threadIdx.x, lane = tid & 31, wid = tid >> 5;
    const uint4* p = reinterpret_cast<const uint4*>(g_wtb + (size_t)row * VVP + seg * SEGLEN);
    const int base = seg * SEGLEN;

    float lv[TK]; int li[TK];
    #pragma unroll
    for (int t = 0; t < TK; t++) { lv[t] = 0.f; li[t] = 0x7fffffff; }
    uint32_t thr = 0, thr2 = 0;          // bf16 bits of lv[TK-1], scalar + packed
    float2 s2 = make_float2(0.f, 0.f);

    for (int ci = tid; ci < NCHUNK; ci += 256) {
        uint4 w = p[ci];
        // sum: exact bf16 -> fp32 via shift/mask (ALU + FMA pipes)
        s2.x += __uint_as_float(w.x << 16);          s2.y += __uint_as_float(w.x & 0xffff0000u);
        s2.x += __uint_as_float(w.y << 16);          s2.y += __uint_as_float(w.y & 0xffff0000u);
        s2.x += __uint_as_float(w.z << 16);          s2.y += __uint_as_float(w.z & 0xffff0000u);
        s2.x += __uint_as_float(w.w << 16);          s2.y += __uint_as_float(w.w & 0xffff0000u);
        // fast-path: packed unsigned max vs threshold (positive bf16 order == uint16 order)
        uint32_t m = __vmaxu2(__vmaxu2(w.x, w.y), __vmaxu2(w.z, w.w));
        if (__vmaxu2(m, thr2) != thr2) {
            uint32_t ws[4] = {w.x, w.y, w.z, w.w};
            #pragma unroll
            for (int j = 0; j < 8; j++) {
                uint32_t bits = (j & 1) ? (ws[j >> 1] >> 16) : (ws[j >> 1] & 0xffffu);
                if (bits > thr) {
                    float e = __uint_as_float(bits << 16);
                    int idx = base + ci * 8 + j;
                    bool gt[TK];
                    #pragma unroll
                    for (int t = 0; t < TK; t++) gt[t] = (e > lv[t]);
                    #pragma unroll
                    for (int t = TK - 1; t >= 1; t--)
                        if (gt[t - 1]) { lv[t] = lv[t - 1]; li[t] = li[t - 1]; }
                    #pragma unroll
                    for (int t = 0; t < TK; t++) {
                        bool pl = gt[t] && (t == 0 || !gt[t - 1]);
                        if (pl) { lv[t] = e; li[t] = idx; }
                    }
                    thr = __float_as_uint(lv[TK - 1]) >> 16;
                    thr2 = thr * 0x10001u;
                }
            }
        }
    }
    float ssum = s2.x + s2.y;
    #pragma unroll
    for (int off = 16; off > 0; off >>= 1) ssum += __shfl_xor_sync(0xffffffff, ssum, off);
    __shared__ float wsum[8];
    if (lane == 0) wsum[wid] = ssum;

    __shared__ float wv8[8][TK];
    __shared__ int   wi8[8][TK];
    unsigned long long head = makekey(lv[0], li[0]);
    for (int r = 0; r < TK; r++) {
        unsigned long long k = head;
        #pragma unroll
        for (int off = 16; off > 0; off >>= 1) {
            unsigned long long o = __shfl_xor_sync(0xffffffff, k, off);
            if (o > k) k = o;
        }
        if (head == k) {
            #pragma unroll
            for (int t = 0; t < TK - 1; t++) { lv[t] = lv[t + 1]; li[t] = li[t + 1]; }
            lv[TK - 1] = 0.f; li[TK - 1] = 0x7fffffff;
            head = makekey(lv[0], li[0]);
        }
        if (lane == 0) {
            wv8[wid][r] = __uint_as_float((unsigned)(k >> 32));
            wi8[wid][r] = (int)(0xFFFFFFFFu - (unsigned)(k & 0xFFFFFFFFu));
        }
    }
    __syncthreads();
    if (tid == 0) {
        float t = 0.f;
        #pragma unroll
        for (int i = 0; i < 8; i++) t += wsum[i];
        g_segsum[row * NSEG + seg] = t;
    }
    if (wid == 0) {
        unsigned long long ck[5];
        #pragma unroll
        for (int j = 0; j < 5; j++) {
            int q = lane * 5 + j;
            ck[j] = makekey(wv8[q / TK][q % TK], wi8[q / TK][q % TK]);
        }
        for (int r = 0; r < TK; r++) {
            unsigned long long best = 0ULL;
            #pragma unroll
            for (int j = 0; j < 5; j++) if (ck[j] > best) best = ck[j];
            unsigned long long k = best;
            #pragma unroll
            for (int off = 16; off > 0; off >>= 1) {
                unsigned long long o = __shfl_xor_sync(0xffffffff, k, off);
                if (o > k) k = o;
            }
            #pragma unroll
            for (int j = 0; j < 5; j++) if (ck[j] == k) ck[j] = 0ULL;
            if (lane == 0) {
                g_cand_v[(row * NSEG + seg) * TK + r] = __uint_as_float((unsigned)(k >> 32));
                g_cand_i[(row * NSEG + seg) * TK + r] = (int)(0xFFFFFFFFu - (unsigned)(k & 0xFFFFFFFFu));
            }
        }
    }
}

// ------------------------- merge NSEG*TK=80 candidates -> top-20, normalize, rowinv --------
__global__ void candmerge_kernel() {
    int row = blockIdx.x;
    int lane = threadIdx.x;
    unsigned long long ck[3];
    #pragma unroll
    for (int j = 0; j < 3; j++) {
        int q = lane * 3 + j;
        ck[j] = (q < NSEG * TK)
              ? makekey(g_cand_v[row * (NSEG * TK) + q], g_cand_i[row * (NSEG * TK) + q])
              : 0ULL;
    }
    float selv[TK]; int seli[TK];
    for (int r = 0; r < TK; r++) {
        unsigned long long best = 0ULL;
        #pragma unroll
        for (int j = 0; j < 3; j++) if (ck[j] > best) best = ck[j];
        unsigned long long k = best;
        #pragma unroll
        for (int off = 16; off > 0; off >>= 1) {
            unsigned long long o = __shfl_xor_sync(0xffffffff, k, off);
            if (o > k) k = o;
        }
        #pragma unroll
        for (int j = 0; j < 3; j++) if (ck[j] == k) ck[j] = 0ULL;
        selv[r] = __uint_as_float((unsigned)(k >> 32));
        seli[r] = (int)(0xFFFFFFFFu - (unsigned)(k & 0xFFFFFFFFu));
    }
    if (lane == 0) {
        float s = 0.f;
        #pragma unroll
        for (int r = 0; r < TK; r++) s += selv[r];
        float inv = 1.f / s, sq = 0.f;
        #pragma unroll
        for (int r = 0; r < TK; r++) {
            float nv = selv[r] * inv;
            g_topv[row * TK + r] = nv;
            g_topi[row * TK + r] = seli[r];
            sq += nv * nv;
        }
        g_sq[row] = sq;
        float bs = 0.f;
        #pragma unroll
        for (int s8 = 0; s8 < NSEG; s8++) bs += g_segsum[row * NSEG + s8];
        g_rowinv[row] = 1.f / bs;
    }
}

// ------------------------- theta' = theta * rowinv[t] -> bf16 padded -------------------------
__global__ void scale_theta(const float* __restrict__ theta) {
    int row = blockIdx.x;
    int t = threadIdx.x;
    if (t < TT)
        g_thb[(size_t)row * TTP + t] = __float2bfloat16(theta[row * TT + t] * g_rowinv[t]);
    else if (t < TTP)
        g_thb[(size_t)row * TTP + t] = __float2bfloat16(0.f);
}

// ------------------------- STDR via sparse gram -------------------------
__global__ void stdr_kernel(float* __restrict__ out_stdr) {
    int i = blockIdx.x;
    int tid = threadIdx.x;
    __shared__ float vi[TK]; __shared__ int ii[TK];
    __shared__ float red[256];
    if (tid < TK) { vi[tid] = g_topv[i * TK + tid]; ii[tid] = g_topi[i * TK + tid]; }
    __syncthreads();
    float part = 0.f;
    float sqi = g_sq[i];
    for (int j = tid; j < TT; j += 256) {
        float g = 0.f;
        for (int b = 0; b < TK; b++) {
            int jb = g_topi[j * TK + b];
            float vb = g_topv[j * TK + b];
            #pragma unroll
            for (int a = 0; a < TK; a++)
                if (ii[a] == jb) g += vi[a] * vb;
        }
        float d2 = sqi + g_sq[j] - 2.f * g;
        part += 0.5f * fmaxf(d2, 0.f);
    }
    red[tid] = part;
    __syncthreads();
    for (int s = 128; s > 0; s >>= 1) {
        if (tid < s) red[tid] += red[tid + s];
        __syncthreads();
    }
    if (tid == 0) atomicAdd(out_stdr, red[0] * (1.f / ((float)TT * (float)TT)));
}

// ------------------------- fused Re: full-K smem, L2-prefetched dbow epilogue -------------
// grid (391, 16), x = vocab (fast / streaming), y = bm.  (13 uniform k16 chunks)
#define LDA 216   // 208 + 8 pad (bf16)
#define LDB 136   // 128 + 8 pad (bf16)

__global__ __launch_bounds__(256, 2) void fused_re_mma(const float* __restrict__ dbow,
                                                       float* __restrict__ Re) {
    extern __shared__ char smraw[];
    __nv_bfloat16* As = (__nv_bfloat16*)smraw;            // 128 x LDA
    __nv_bfloat16* Bs = As + 128 * LDA;                   // 208 x LDB

    const int tid = threadIdx.x, lane = tid & 31, wid = tid >> 5;
    const int warp_m = wid >> 2, warp_n = wid & 3;
    const int bm = blockIdx.y * 128;
    const int vb = blockIdx.x * 128;

    // L2-prefetch the dbow tile (128 rows x 512B = 512 cache lines; 2 per thread).
    #pragma unroll
    for (int i = 0; i < 2; i++) {
        int l = tid * 2 + i;
        int row = l >> 2, seg = l & 3;
        int col = vb + seg * 32;
        if (col + 32 <= VV)
            prefetch_l2(dbow + (size_t)(bm + row) * VV + col);
    }

    // load full A tile (128 x 208 bf16) and B tile (208 x 128 bf16)
    #pragma unroll
    for (int i = 0; i < 13; i++) {
        int idx = tid + i * 256;
        int row = idx / 26, u = idx % 26;
        uint4 v = *reinterpret_cast<const uint4*>(g_thb + (size_t)(bm + row) * TTP + u * 8);
        *reinterpret_cast<uint4*>(As + row * LDA + u * 8) = v;
    }
    #pragma unroll
    for (int i = 0; i < 13; i++) {
        int idx = tid + i * 256;
        int k = idx >> 4, u = idx & 15;
        uint4 v = *reinterpret_cast<const uint4*>(g_wtb + (size_t)k * VVP + vb + u * 8);
        *reinterpret_cast<uint4*>(Bs + k * LDB + u * 8) = v;
    }
    __syncthreads();

    // mainloop: 13 uniform k16 chunks, pure smem
    float acc[4][4][4] = {};
    const uint32_t a_base = smem_u32(As) +
        ((warp_m * 64 + (lane & 15)) * LDA + (lane >> 4) * 8) * 2;
    const uint32_t b_base = smem_u32(Bs) +
        (((lane & 7) + ((lane >> 3) & 1) * 8) * LDB + warp_n * 32 + (lane >> 4) * 8) * 2;

    #pragma unroll
    for (int kc = 0; kc < 13; kc++) {
        uint32_t a[4][4], b[4][2];
        #pragma unroll
        for (int mi = 0; mi < 4; mi++)
            ldsm_x4(a[mi][0], a[mi][1], a[mi][2], a[mi][3],
                    a_base + mi * 16 * LDA * 2 + kc * 32);
        uint32_t bb = b_base + kc * 16 * LDB * 2;
        ldsm_x4(b[0][0], b[0][1], b[1][0], b[1][1], bb);
        ldsm_x4(b[2][0], b[2][1], b[3][0], b[3][1], bb + 32);
        #pragma unroll
        for (int mi = 0; mi < 4; mi++)
            #pragma unroll
            for (int ni = 0; ni < 4; ni++)
                mma_bf16(acc[mi][ni], a[mi], b[ni]);
    }
    __syncthreads();

    // epilogue: dbow (L2-warm) direct from global, -log(logit)*dbow, per-row reduce
    float* sre = (float*)As;   // reuse A region
    if (tid < 128) sre[tid] = 0.f;
    __syncthreads();

    #pragma unroll
    for (int mi = 0; mi < 4; mi++) {
        int r0 = bm + warp_m * 64 + mi * 16 + (lane >> 2);
        float p0 = 0.f, p1 = 0.f;
        #pragma unroll
        for (int ni = 0; ni < 4; ni++) {
            int n0 = vb + warp_n * 32 + ni * 8 + (lane & 3) * 2;
            if (n0 < VV) {
                float2 d0 = *reinterpret_cast<const float2*>(dbow + (size_t)r0 * VV + n0);
                float2 d1 = *reinterpret_cast<const float2*>(dbow + (size_t)(r0 + 8) * VV + n0);
                p0 -= __logf(acc[mi][ni][0]) * d0.x + __logf(acc[mi][ni][1]) * d0.y;
                p1 -= __logf(acc[mi][ni][2]) * d1.x + __logf(acc[mi][ni][3]) * d1.y;
            }
        }
        p0 += __shfl_xor_sync(0xffffffff, p0, 1);
        p0 += __shfl_xor_sync(0xffffffff, p0, 2);
        p1 += __shfl_xor_sync(0xffffffff, p1, 1);
        p1 += __shfl_xor_sync(0xffffffff, p1, 2);
        if ((lane & 3) == 0) {
            int rl = warp_m * 64 + mi * 16 + (lane >> 2);
            atomicAdd(&sre[rl], p0);
            atomicAdd(&sre[rl + 8], p1);
        }
    }
    __syncthreads();
    if (tid < 128) atomicAdd(&Re[bm + tid], sre[tid]);
}

// ------------------------- launch -------------------------
extern "C" void kernel_launch(void* const* d_in, const int* in_sizes, int n_in,
                              void* d_out, int out_size) {
    (void)in_sizes; (void)n_in; (void)out_size;
    const float* alpha = (const float*)d_in[0];
    const float* dbow  = (const float*)d_in[1];
    const float* temb  = (const float*)d_in[2];
    const float* wemb  = (const float*)d_in[3];
    float* out   = (float*)d_out;
    float* Re    = out;            // [0 .. 2047]
    float* stdr  = out + BB;       // [2048]
    float* theta = out + BB + 1;   // [2049 ...]

    cudaMemsetAsync(out, 0, (BB + 1) * sizeof(float));
    theta_kernel<<<BB, 256>>>(alpha, theta);
    conv_ta<<<(256 * KEMB + 255) / 256, 256>>>(temb);

    wt_mma_kernel<<<dim3((VV + 127) / 128, 2), 256>>>(wemb);

    expsum_topk_seg<<<dim3(NSEG, TT), 256>>>();
    candmerge_kernel<<<TT, 32>>>();
    scale_theta<<<BB, 256>>>(theta);
    stdr_kernel<<<TT, 256>>>(stdr);

    {
        size_t sm = (size_t)128 * LDA * 2 + (size_t)TTP * LDB * 2;
        cudaFuncSetAttribute(fused_re_mma,
                             cudaFuncAttributeMaxDynamicSharedMemorySize, (int)sm);
        fused_re_mma<<<dim3((VV + 127) / 128, BB / 128), 256, sm>>>(dbow, Re);
    }
}